// round 2
// baseline (speedup 1.0000x reference)
#include <cuda_runtime.h>
#include <cuda_bf16.h>
#include <cstdint>

// Problem constants (fixed by the dataset)
#define C_DIM 128   // input feature dim
#define H_DIM 64    // hidden dim
#define E_FEAT 16   // edge feature dim
#define ATT_LD 144  // 2*H + E_FEAT

#define MAXN 65536

// Scratch: per-node projected features and attention partials
__device__ float g_h[MAXN * H_DIM];       // h = fc(x)          [N,64]
__device__ float g_a12[MAXN * 2 * H_DIM]; // [a1 | a2]          [N,128]
__device__ int   g_idx64;                 // 1 if edge_index is int64, 0 if int32

// ---------------------------------------------------------------------------
// Detect edge_index dtype. Real int64 indices are all in [0, N); an int32
// buffer reinterpreted as int64 has a random high word, so some value lands
// outside [0, N) within the first 128 entries with probability ~1.
// ---------------------------------------------------------------------------
__global__ void detect_idx_kernel(const long long* __restrict__ ei, int N)
{
    if (threadIdx.x == 0 && blockIdx.x == 0) {
        int is64 = 1;
        for (int k = 0; k < 128; k++) {
            long long v = ei[k];
            if (v < 0 || v >= (long long)N) { is64 = 0; break; }
        }
        g_idx64 = is64;
    }
}

// ---------------------------------------------------------------------------
// Tiled fp32 GEMM with optional bias:
//   out[m, ooff + n] = sum_k A[m*lda + k0+k] * W[n*ldw + woff + k] (+ bias[n])
// BM=128, BN=64, BK=16, 256 threads, 8x4 microtile per thread.
// ---------------------------------------------------------------------------
#define BM 128
#define BN 64
#define BK 16

__global__ __launch_bounds__(256) void gemm_bias_kernel(
    const float* __restrict__ A, int lda,
    const float* __restrict__ W, int ldw, int woff,
    const float* __restrict__ bias,
    float* __restrict__ out, int ldo, int ooff,
    int M, int K)
{
    __shared__ float As[BM][BK + 4];  // row stride 20 floats (80B, keeps 16B alignment)
    __shared__ float Bs[BK][BN];

    const int tid = threadIdx.x;
    const int bm = blockIdx.x * BM;
    const int tx = tid & 15;        // col group tx*4
    const int ty = tid >> 4;        // row group ty*8

    float acc[8][4];
#pragma unroll
    for (int r = 0; r < 8; r++)
#pragma unroll
        for (int c = 0; c < 4; c++) acc[r][c] = 0.f;

    for (int k0 = 0; k0 < K; k0 += BK) {
        // A tile: 128 x 16 floats, 2 x float4 per thread
#pragma unroll
        for (int it = 0; it < 2; it++) {
            int m = (tid >> 2) + it * 64;
            int kk = (tid & 3) * 4;
            float4 v = make_float4(0.f, 0.f, 0.f, 0.f);
            if (bm + m < M)
                v = *(const float4*)&A[(size_t)(bm + m) * lda + k0 + kk];
            *(float4*)&As[m][kk] = v;
        }
        // W tile transposed: 16 x 64, 1 x float4 per thread
        {
            int n = tid >> 2;            // 0..63
            int kk = (tid & 3) * 4;      // 0,4,8,12
            float4 v = *(const float4*)&W[(size_t)n * ldw + woff + k0 + kk];
            Bs[kk + 0][n] = v.x;
            Bs[kk + 1][n] = v.y;
            Bs[kk + 2][n] = v.z;
            Bs[kk + 3][n] = v.w;
        }
        __syncthreads();

#pragma unroll
        for (int kk = 0; kk < BK; kk++) {
            float b4[4];
            *(float4*)b4 = *(const float4*)&Bs[kk][tx * 4];
            float a8[8];
#pragma unroll
            for (int r = 0; r < 8; r++) a8[r] = As[ty * 8 + r][kk];
#pragma unroll
            for (int r = 0; r < 8; r++)
#pragma unroll
                for (int c = 0; c < 4; c++)
                    acc[r][c] = fmaf(a8[r], b4[c], acc[r][c]);
        }
        __syncthreads();
    }

#pragma unroll
    for (int r = 0; r < 8; r++) {
        int m = bm + ty * 8 + r;
        if (m < M) {
#pragma unroll
            for (int c = 0; c < 4; c++) {
                int n = tx * 4 + c;
                float v = acc[r][c];
                if (bias) v += bias[n];
                out[(size_t)m * ldo + ooff + n] = v;
            }
        }
    }
}

// ---------------------------------------------------------------------------
// Zero the output buffer (harness poisons it with 0xAA).
// ---------------------------------------------------------------------------
__global__ void zero_kernel(float* __restrict__ out, int n)
{
    int i = blockIdx.x * blockDim.x + threadIdx.x;
    if (i < n) out[i] = 0.f;
}

// ---------------------------------------------------------------------------
// Edge phase: one warp per edge (grid-stride).
//   alpha = leaky( a1[i] + a2[j] + W3 @ ea[e] + att_b )
//   atomically: out[i] += h[j] * alpha
// Lane owns output channels k0=2*lane, k0+1. W3 rows for those channels live
// in registers. edge_attr loaded by lanes 0..15, broadcast via shuffles.
// Index dtype (int32 vs int64) selected by runtime flag g_idx64.
// ---------------------------------------------------------------------------
__global__ __launch_bounds__(256) void edge_kernel(
    const void* __restrict__ ei_raw,    // [2,E] int32 or int64
    const float* __restrict__ ea,       // [E,16]
    const float* __restrict__ att_w,    // [64,144]
    const float* __restrict__ att_b,    // [64]
    const float* __restrict__ h,        // [N,64]
    const float* __restrict__ a12,      // [N,128] = [a1|a2]
    float* __restrict__ out,            // [N,64]
    int E)
{
    const int lane = threadIdx.x & 31;
    const int warp = blockIdx.x * (blockDim.x >> 5) + (threadIdx.x >> 5);
    const int nwarps = gridDim.x * (blockDim.x >> 5);
    const int k0 = 2 * lane;

    const int is64 = g_idx64;
    const long long* ei64 = (const long long*)ei_raw;
    const int*       ei32 = (const int*)ei_raw;

    // W3 rows for this lane's two output channels, plus bias — registers.
    float w3a[E_FEAT], w3b[E_FEAT];
#pragma unroll
    for (int c = 0; c < E_FEAT; c++) {
        w3a[c] = att_w[(size_t)k0 * ATT_LD + 2 * H_DIM + c];
        w3b[c] = att_w[(size_t)(k0 + 1) * ATT_LD + 2 * H_DIM + c];
    }
    const float b0 = att_b[k0];
    const float b1 = att_b[k0 + 1];

    for (int e = warp; e < E; e += nwarps) {
        int i, j;
        if (is64) {
            i = (int)ei64[e];
            j = (int)ei64[E + e];
        } else {
            i = ei32[e];
            j = ei32[E + e];
        }

        float eav = (lane < E_FEAT) ? ea[(size_t)e * E_FEAT + lane] : 0.f;

        const float2 A1 = *(const float2*)&a12[(size_t)i * (2 * H_DIM) + k0];
        const float2 A2 = *(const float2*)&a12[(size_t)j * (2 * H_DIM) + H_DIM + k0];
        const float2 HJ = *(const float2*)&h[(size_t)j * H_DIM + k0];

        float sx = A1.x + A2.x + b0;
        float sy = A1.y + A2.y + b1;
#pragma unroll
        for (int c = 0; c < E_FEAT; c++) {
            float ec = __shfl_sync(0xffffffffu, eav, c);
            sx = fmaf(w3a[c], ec, sx);
            sy = fmaf(w3b[c], ec, sy);
        }
        // leaky_relu, slope 0.2
        sx = fmaxf(sx, 0.f) + 0.2f * fminf(sx, 0.f);
        sy = fmaxf(sy, 0.f) + 0.2f * fminf(sy, 0.f);

        atomicAdd(&out[(size_t)i * H_DIM + k0],     HJ.x * sx);
        atomicAdd(&out[(size_t)i * H_DIM + k0 + 1], HJ.y * sy);
    }
}

// ---------------------------------------------------------------------------
// Launch
// Inputs (metadata order): x, edge_index, edge_attr, fc_w, fc_b, att_w, att_b
// ---------------------------------------------------------------------------
extern "C" void kernel_launch(void* const* d_in, const int* in_sizes, int n_in,
                              void* d_out, int out_size)
{
    const float* x     = (const float*)d_in[0];
    const void*  ei    = d_in[1];
    const float* ea    = (const float*)d_in[2];
    const float* fc_w  = (const float*)d_in[3];
    const float* fc_b  = (const float*)d_in[4];
    const float* att_w = (const float*)d_in[5];
    const float* att_b = (const float*)d_in[6];
    float*       out   = (float*)d_out;

    const int N = in_sizes[0] / C_DIM;
    const int E = in_sizes[1] / 2;

    float* hbuf = nullptr;
    float* a12buf = nullptr;
    cudaGetSymbolAddress((void**)&hbuf, g_h);
    cudaGetSymbolAddress((void**)&a12buf, g_a12);

    // Detect index dtype (device-side, deterministic, graph-capturable)
    detect_idx_kernel<<<1, 32>>>((const long long*)ei, N);

    const int gblocks = (N + BM - 1) / BM;

    // h = x @ fc_w^T + fc_b          [N,64]
    gemm_bias_kernel<<<gblocks, 256>>>(x, C_DIM, fc_w, C_DIM, 0, fc_b,
                                       hbuf, H_DIM, 0, N, C_DIM);
    // a1 = h @ W1^T   (att_w cols [0,64))
    gemm_bias_kernel<<<gblocks, 256>>>(hbuf, H_DIM, att_w, ATT_LD, 0, nullptr,
                                       a12buf, 2 * H_DIM, 0, N, H_DIM);
    // a2 = h @ W2^T   (att_w cols [64,128))
    gemm_bias_kernel<<<gblocks, 256>>>(hbuf, H_DIM, att_w, ATT_LD, H_DIM, nullptr,
                                       a12buf, 2 * H_DIM, H_DIM, N, H_DIM);

    // zero output, then scatter
    const int nout = N * H_DIM;
    zero_kernel<<<(nout + 255) / 256, 256>>>(out, nout);

    edge_kernel<<<1184, 256>>>(ei, ea, att_w, att_b, hbuf, a12buf, out, E);
}

// round 3
// speedup vs baseline: 1.4285x; 1.4285x over previous
#include <cuda_runtime.h>
#include <cuda_bf16.h>
#include <cstdint>

// Problem constants (fixed by the dataset)
#define C_DIM 128   // input feature dim
#define H_DIM 64    // hidden dim
#define E_FEAT 16   // edge feature dim
#define ATT_LD 144  // 2*H + E_FEAT

#define MAXN 65536

// Scratch: per-node projected features and attention partials
__device__ float g_h[MAXN * H_DIM];       // h = fc(x)          [N,64]
__device__ float g_a12[MAXN * 2 * H_DIM]; // [a1 | a2]          [N,128]
__device__ int   g_idx64;                 // 1 if edge_index is int64, 0 if int32

// ---------------------------------------------------------------------------
// Detect edge_index dtype. Real int64 indices are all in [0, N); an int32
// buffer reinterpreted as int64 has a random high word, so some value lands
// outside [0, N) within the first 128 entries with probability ~1.
// ---------------------------------------------------------------------------
__global__ void detect_idx_kernel(const long long* __restrict__ ei, int N)
{
    if (threadIdx.x == 0 && blockIdx.x == 0) {
        int is64 = 1;
        for (int k = 0; k < 128; k++) {
            long long v = ei[k];
            if (v < 0 || v >= (long long)N) { is64 = 0; break; }
        }
        g_idx64 = is64;
    }
}

// ---------------------------------------------------------------------------
// GEMM 1: h = x @ fc_w^T + fc_b. BM=128, BN=64, BK=16, 256 thr, 8x4 microtile.
// ---------------------------------------------------------------------------
#define BM 128
#define BK 16

__global__ __launch_bounds__(256) void gemm_h_kernel(
    const float* __restrict__ A,      // [M,128]
    const float* __restrict__ W,      // [64,128]
    const float* __restrict__ bias,   // [64]
    float* __restrict__ out,          // [M,64]
    int M)
{
    __shared__ float As[BM][BK + 4];
    __shared__ float Bs[BK][64];

    const int tid = threadIdx.x;
    const int bm = blockIdx.x * BM;
    const int tx = tid & 15;        // col group tx*4
    const int ty = tid >> 4;        // row group ty*8

    float acc[8][4];
#pragma unroll
    for (int r = 0; r < 8; r++)
#pragma unroll
        for (int c = 0; c < 4; c++) acc[r][c] = 0.f;

    for (int k0 = 0; k0 < C_DIM; k0 += BK) {
#pragma unroll
        for (int it = 0; it < 2; it++) {
            int m = (tid >> 2) + it * 64;
            int kk = (tid & 3) * 4;
            float4 v = make_float4(0.f, 0.f, 0.f, 0.f);
            if (bm + m < M)
                v = *(const float4*)&A[(size_t)(bm + m) * C_DIM + k0 + kk];
            *(float4*)&As[m][kk] = v;
        }
        {
            int n = tid >> 2;            // 0..63
            int kk = (tid & 3) * 4;      // 0,4,8,12
            float4 v = *(const float4*)&W[(size_t)n * C_DIM + k0 + kk];
            Bs[kk + 0][n] = v.x;
            Bs[kk + 1][n] = v.y;
            Bs[kk + 2][n] = v.z;
            Bs[kk + 3][n] = v.w;
        }
        __syncthreads();

#pragma unroll
        for (int kk = 0; kk < BK; kk++) {
            float b4[4];
            *(float4*)b4 = *(const float4*)&Bs[kk][tx * 4];
            float a8[8];
#pragma unroll
            for (int r = 0; r < 8; r++) a8[r] = As[ty * 8 + r][kk];
#pragma unroll
            for (int r = 0; r < 8; r++)
#pragma unroll
                for (int c = 0; c < 4; c++)
                    acc[r][c] = fmaf(a8[r], b4[c], acc[r][c]);
        }
        __syncthreads();
    }

#pragma unroll
    for (int r = 0; r < 8; r++) {
        int m = bm + ty * 8 + r;
        if (m < M) {
#pragma unroll
            for (int c = 0; c < 4; c++) {
                int n = tx * 4 + c;
                out[(size_t)m * H_DIM + n] = acc[r][c] + bias[n];
            }
        }
    }
}

// ---------------------------------------------------------------------------
// GEMM 2 (fused a1|a2): a12[n, q] for q in [0,128):
//   q <  64: sum_m h[n,m] * att_w[q][m]
//   q >= 64: sum_m h[n,m] * att_w[q-64][64+m]
// Weight element for output col q, k index m: att_w[(q&63)*144 + (q>>6)*64 + m]
// BM=128, BN=128, BK=16, K=64, 256 threads, 8x8 microtile.
// ---------------------------------------------------------------------------
__global__ __launch_bounds__(256) void gemm_a12_kernel(
    const float* __restrict__ h,      // [M,64]
    const float* __restrict__ att_w,  // [64,144]
    float* __restrict__ a12,          // [M,128]
    int M)
{
    __shared__ float As[BM][BK + 4];
    __shared__ float Bs[BK][128];

    const int tid = threadIdx.x;
    const int bm = blockIdx.x * BM;
    const int tx = tid & 15;        // col group tx*8
    const int ty = tid >> 4;        // row group ty*8

    float acc[8][8];
#pragma unroll
    for (int r = 0; r < 8; r++)
#pragma unroll
        for (int c = 0; c < 8; c++) acc[r][c] = 0.f;

    for (int k0 = 0; k0 < H_DIM; k0 += BK) {
        // A tile: 128 x 16
#pragma unroll
        for (int it = 0; it < 2; it++) {
            int m = (tid >> 2) + it * 64;
            int kk = (tid & 3) * 4;
            float4 v = make_float4(0.f, 0.f, 0.f, 0.f);
            if (bm + m < M)
                v = *(const float4*)&h[(size_t)(bm + m) * H_DIM + k0 + kk];
            *(float4*)&As[m][kk] = v;
        }
        // B tile: 16 x 128 (transposed store). Thread: q = tid>>1, 8 k's.
        {
            int q = tid >> 1;                 // 0..127
            int kk = (tid & 1) * 8;           // 0 or 8
            size_t base = (size_t)(q & 63) * ATT_LD + (q >> 6) * 64 + k0 + kk;
            float4 v0 = *(const float4*)&att_w[base];
            float4 v1 = *(const float4*)&att_w[base + 4];
            Bs[kk + 0][q] = v0.x; Bs[kk + 1][q] = v0.y;
            Bs[kk + 2][q] = v0.z; Bs[kk + 3][q] = v0.w;
            Bs[kk + 4][q] = v1.x; Bs[kk + 5][q] = v1.y;
            Bs[kk + 6][q] = v1.z; Bs[kk + 7][q] = v1.w;
        }
        __syncthreads();

#pragma unroll
        for (int kk = 0; kk < BK; kk++) {
            float b8[8];
            *(float4*)&b8[0] = *(const float4*)&Bs[kk][tx * 8];
            *(float4*)&b8[4] = *(const float4*)&Bs[kk][tx * 8 + 4];
            float a8[8];
#pragma unroll
            for (int r = 0; r < 8; r++) a8[r] = As[ty * 8 + r][kk];
#pragma unroll
            for (int r = 0; r < 8; r++)
#pragma unroll
                for (int c = 0; c < 8; c++)
                    acc[r][c] = fmaf(a8[r], b8[c], acc[r][c]);
        }
        __syncthreads();
    }

#pragma unroll
    for (int r = 0; r < 8; r++) {
        int m = bm + ty * 8 + r;
        if (m < M) {
            float* dst = &a12[(size_t)m * 128 + tx * 8];
            *(float4*)&dst[0] = *(float4*)&acc[r][0];
            *(float4*)&dst[4] = *(float4*)&acc[r][4];
        }
    }
}

// ---------------------------------------------------------------------------
// Zero the output buffer (float4).
// ---------------------------------------------------------------------------
__global__ void zero_kernel(float4* __restrict__ out, int n4)
{
    int i = blockIdx.x * blockDim.x + threadIdx.x;
    if (i < n4) out[i] = make_float4(0.f, 0.f, 0.f, 0.f);
}

// ---------------------------------------------------------------------------
// Edge phase v2: HALF-WARP per edge, 4 channels per lane (float4).
//   alpha = leaky( a1[i] + a2[j] + W3 @ ea[e] + att_b )
//   out[i] += h[j] * alpha      (red.global.add.v4.f32)
// 2x unrolled grid-stride loop with warp-uniform bounds (shuffles stay safe).
// ---------------------------------------------------------------------------
__device__ __forceinline__ float4 leaky4(float4 s)
{
    s.x = fmaxf(s.x, 0.f) + 0.2f * fminf(s.x, 0.f);
    s.y = fmaxf(s.y, 0.f) + 0.2f * fminf(s.y, 0.f);
    s.z = fmaxf(s.z, 0.f) + 0.2f * fminf(s.z, 0.f);
    s.w = fmaxf(s.w, 0.f) + 0.2f * fminf(s.w, 0.f);
    return s;
}

__device__ __forceinline__ void red_add_v4(float* p, float4 v)
{
    asm volatile("red.global.add.v4.f32 [%0], {%1, %2, %3, %4};"
                 :: "l"(p), "f"(v.x), "f"(v.y), "f"(v.z), "f"(v.w)
                 : "memory");
}

__global__ __launch_bounds__(256) void edge_kernel_v2(
    const void* __restrict__ ei_raw,    // [2,E] int32 or int64
    const float* __restrict__ ea,       // [E,16]
    const float* __restrict__ att_w,    // [64,144]
    const float* __restrict__ att_b,    // [64]
    const float* __restrict__ h,        // [N,64]
    const float* __restrict__ a12,      // [N,128] = [a1|a2]
    float* __restrict__ out,            // [N,64]
    int E)
{
    __shared__ float W3s[E_FEAT][H_DIM]; // W3s[c][k] = att_w[k][128+c]

    const int tid  = threadIdx.x;
    const int lane = tid & 31;
    const int group = lane >> 4;        // half-warp id within warp
    const int glane = lane & 15;        // lane within half-warp
    const int warp = blockIdx.x * (blockDim.x >> 5) + (tid >> 5);
    const int nwarps = gridDim.x * (blockDim.x >> 5);
    const int stride = nwarps * 2;      // total half-warps
    const int k0 = 4 * glane;           // this lane's 4 output channels

    // Load W3 transpose into smem (once per block)
    for (int idx = tid; idx < E_FEAT * H_DIM; idx += blockDim.x) {
        int c = idx >> 6;   // 0..15
        int k = idx & 63;   // 0..63
        W3s[c][k] = att_w[(size_t)k * ATT_LD + 2 * H_DIM + c];
    }
    __syncthreads();

    const int is64 = g_idx64;
    const long long* ei64 = (const long long*)ei_raw;
    const int*       ei32 = (const int*)ei_raw;
    const float4* a12_4 = (const float4*)a12;  // [N][32]
    const float4* h4    = (const float4*)h;    // [N][16]
    const float4* W3s4  = (const float4*)&W3s[0][0]; // [16][16]

    const float4 bias4 = *(const float4*)&att_b[k0];
    const int shfl_base = group << 4;

    for (long long eb = 2 * (long long)warp; eb < E; eb += 2 * (long long)stride) {
        int e1 = (int)eb + group;
        int e2 = (int)eb + stride + group;
        const bool v1 = e1 < E;
        const bool v2 = e2 < E;
        const int e1c = v1 ? e1 : 0;
        const int e2c = v2 ? e2 : 0;

        int i1, j1, i2, j2;
        if (is64) {
            i1 = (int)ei64[e1c]; j1 = (int)ei64[(size_t)E + e1c];
            i2 = (int)ei64[e2c]; j2 = (int)ei64[(size_t)E + e2c];
        } else {
            i1 = ei32[e1c]; j1 = ei32[(size_t)E + e1c];
            i2 = ei32[e2c]; j2 = ei32[(size_t)E + e2c];
        }

        float eav1 = ea[(size_t)e1c * E_FEAT + glane];
        float eav2 = ea[(size_t)e2c * E_FEAT + glane];

        float4 A1a = a12_4[(size_t)i1 * 32 + glane];
        float4 A2a = a12_4[(size_t)j1 * 32 + 16 + glane];
        float4 HJa = h4[(size_t)j1 * 16 + glane];
        float4 A1b = a12_4[(size_t)i2 * 32 + glane];
        float4 A2b = a12_4[(size_t)j2 * 32 + 16 + glane];
        float4 HJb = h4[(size_t)j2 * 16 + glane];

        float4 s1, s2;
        s1.x = bias4.x + A1a.x + A2a.x;  s2.x = bias4.x + A1b.x + A2b.x;
        s1.y = bias4.y + A1a.y + A2a.y;  s2.y = bias4.y + A1b.y + A2b.y;
        s1.z = bias4.z + A1a.z + A2a.z;  s2.z = bias4.z + A1b.z + A2b.z;
        s1.w = bias4.w + A1a.w + A2a.w;  s2.w = bias4.w + A1b.w + A2b.w;

#pragma unroll
        for (int c = 0; c < E_FEAT; c++) {
            float ec1 = __shfl_sync(0xffffffffu, eav1, shfl_base + c);
            float ec2 = __shfl_sync(0xffffffffu, eav2, shfl_base + c);
            float4 w4 = W3s4[c * 16 + glane];
            s1.x = fmaf(w4.x, ec1, s1.x);  s2.x = fmaf(w4.x, ec2, s2.x);
            s1.y = fmaf(w4.y, ec1, s1.y);  s2.y = fmaf(w4.y, ec2, s2.y);
            s1.z = fmaf(w4.z, ec1, s1.z);  s2.z = fmaf(w4.z, ec2, s2.z);
            s1.w = fmaf(w4.w, ec1, s1.w);  s2.w = fmaf(w4.w, ec2, s2.w);
        }

        s1 = leaky4(s1);
        s2 = leaky4(s2);

        if (v1) {
            float4 m1 = make_float4(HJa.x * s1.x, HJa.y * s1.y,
                                    HJa.z * s1.z, HJa.w * s1.w);
            red_add_v4(&out[(size_t)i1 * H_DIM + k0], m1);
        }
        if (v2) {
            float4 m2 = make_float4(HJb.x * s2.x, HJb.y * s2.y,
                                    HJb.z * s2.z, HJb.w * s2.w);
            red_add_v4(&out[(size_t)i2 * H_DIM + k0], m2);
        }
    }
}

// ---------------------------------------------------------------------------
// Launch
// Inputs (metadata order): x, edge_index, edge_attr, fc_w, fc_b, att_w, att_b
// ---------------------------------------------------------------------------
extern "C" void kernel_launch(void* const* d_in, const int* in_sizes, int n_in,
                              void* d_out, int out_size)
{
    const float* x     = (const float*)d_in[0];
    const void*  ei    = d_in[1];
    const float* ea    = (const float*)d_in[2];
    const float* fc_w  = (const float*)d_in[3];
    const float* fc_b  = (const float*)d_in[4];
    const float* att_w = (const float*)d_in[5];
    const float* att_b = (const float*)d_in[6];
    float*       out   = (float*)d_out;

    const int N = in_sizes[0] / C_DIM;
    const int E = in_sizes[1] / 2;

    float* hbuf = nullptr;
    float* a12buf = nullptr;
    cudaGetSymbolAddress((void**)&hbuf, g_h);
    cudaGetSymbolAddress((void**)&a12buf, g_a12);

    detect_idx_kernel<<<1, 32>>>((const long long*)ei, N);

    const int gblocks = (N + BM - 1) / BM;

    // h = x @ fc_w^T + fc_b          [N,64]
    gemm_h_kernel<<<gblocks, 256>>>(x, fc_w, fc_b, hbuf, N);
    // a12 = h @ [W1|W2]^T            [N,128]
    gemm_a12_kernel<<<gblocks, 256>>>(hbuf, att_w, a12buf, N);

    // zero output (float4), then scatter
    const int n4 = (N * H_DIM) / 4;
    zero_kernel<<<(n4 + 255) / 256, 256>>>((float4*)out, n4);

    edge_kernel_v2<<<1184, 256>>>(ei, ea, att_w, att_b, hbuf, a12buf, out, E);
}